// round 1
// baseline (speedup 1.0000x reference)
#include <cuda_runtime.h>

#define Bb   128
#define Ss   416
#define Nn   32
#define Mm   384
#define Dd   256
#define Hh   8
#define Ee   32
#define Oo   256
#define BSs  (Bb*Ss)          // 53248

// -------- scratch (static device globals; no runtime allocation) ----------
__device__ float g_xln[BSs*Dd];        // LN1(x)
__device__ float g_q  [Bb*Hh*Ss*Ee];
__device__ float g_k  [Bb*Hh*Ss*Ee];
__device__ float g_v  [Bb*Hh*Ss*Ee];
__device__ float g_g  [Bb*Hh*Ss*Ee];
__device__ float g_ao [BSs*Oo];        // attention output, [B,S,H*E]

__device__ __forceinline__ float warpSum(float v) {
#pragma unroll
    for (int o = 16; o; o >>= 1) v += __shfl_xor_sync(0xffffffffu, v, o);
    return v;
}
__device__ __forceinline__ float warpMax(float v) {
#pragma unroll
    for (int o = 16; o; o >>= 1) v = fmaxf(v, __shfl_xor_sync(0xffffffffu, v, o));
    return v;
}

// =================== Kernel 1: LayerNorm over D=256 =======================
__global__ void k_ln1(const float* __restrict__ x,
                      const float* __restrict__ gam,
                      const float* __restrict__ bet) {
    int row = blockIdx.x;            // 0..BSs-1
    int t = threadIdx.x;             // 0..255
    int w = t >> 5, lane = t & 31;
    __shared__ float red[8];

    float v = x[(size_t)row * Dd + t];
    float s = warpSum(v);
    if (lane == 0) red[w] = s;
    __syncthreads();
    float mu = 0.f;
#pragma unroll
    for (int i = 0; i < 8; i++) mu += red[i];
    mu *= (1.f / 256.f);
    float d = v - mu;
    __syncthreads();
    s = warpSum(d * d);
    if (lane == 0) red[w] = s;
    __syncthreads();
    float var = 0.f;
#pragma unroll
    for (int i = 0; i < 8; i++) var += red[i];
    var *= (1.f / 256.f);
    g_xln[(size_t)row * Dd + t] = d * rsqrtf(var + 1e-6f) * gam[t] + bet[t];
}

// ============ Kernel 2: QKVG projections as tiled SGEMM ====================
// C[53248 x 1024] = xln[53248 x 256] * W[256 x 1024]; 4 projections of 256
// cols each. Block tile 64x64, BK=16, 4x4 micro-tile, 256 threads.
__global__ void k_qkvg(const float* __restrict__ qp, const float* __restrict__ kp,
                       const float* __restrict__ vp, const float* __restrict__ gp) {
    __shared__ float As[16][68];   // [k][m], padded
    __shared__ float Bs[16][64];   // [k][n]

    int tid = threadIdx.x;
    int tx = tid & 15, ty = tid >> 4;
    int m0 = blockIdx.x * 64;          // row tile (832 tiles)
    int n0 = blockIdx.y * 64;          // col tile (16 tiles over 1024 cols)
    int proj = n0 >> 8;                // 0..3
    const float* W = (proj == 0) ? qp : (proj == 1) ? kp : (proj == 2) ? vp : gp;
    float*      Og = (proj == 0) ? g_q : (proj == 1) ? g_k : (proj == 2) ? g_v : g_g;
    int nin = n0 & 255;                // col within projection (multiple of 64)

    float acc[4][4] = {};
    for (int k0 = 0; k0 < 256; k0 += 16) {
        // A tile 64x16  (A[m][k] -> As[k][m])
#pragma unroll
        for (int i = tid; i < 64 * 16; i += 256) {
            int m = i >> 4, kk = i & 15;
            As[kk][m] = g_xln[(size_t)(m0 + m) * Dd + k0 + kk];
        }
        // B tile 16x64 : column nn -> (h = nn>>5, e = nn&31), W[h][k][e]
#pragma unroll
        for (int i = tid; i < 16 * 64; i += 256) {
            int kk = i >> 6, n = i & 63;
            int nn = nin + n;
            Bs[kk][n] = W[((nn >> 5) << 13) + (k0 + kk) * 32 + (nn & 31)];
        }
        __syncthreads();
#pragma unroll
        for (int kk = 0; kk < 16; kk++) {
            float4 b4 = *(const float4*)&Bs[kk][tx * 4];
            float a[4];
#pragma unroll
            for (int i = 0; i < 4; i++) a[i] = As[kk][ty * 4 + i];
#pragma unroll
            for (int i = 0; i < 4; i++) {
                acc[i][0] = fmaf(a[i], b4.x, acc[i][0]);
                acc[i][1] = fmaf(a[i], b4.y, acc[i][1]);
                acc[i][2] = fmaf(a[i], b4.z, acc[i][2]);
                acc[i][3] = fmaf(a[i], b4.w, acc[i][3]);
            }
        }
        __syncthreads();
    }
#pragma unroll
    for (int i = 0; i < 4; i++) {
        int m = m0 + ty * 4 + i;
        int b = m / Ss;
        int s = m - b * Ss;
#pragma unroll
        for (int j = 0; j < 4; j++) {
            int nn = nin + tx * 4 + j;
            int h = nn >> 5, e = nn & 31;
            Og[(((size_t)(b * Hh + h)) * Ss + s) * Ee + e] = acc[i][j];
        }
    }
}

// ============ Kernel 3: fused attention per (b, h, 32-row x tile) =========
// smem: q[32*32] | kT[32*420] | att[32*416] | c[416]  = 112768 bytes
__global__ void k_attn(const float* __restrict__ pmask,
                       const float* __restrict__ mmask) {
    extern __shared__ float sm[];
    float* q_sh = sm;                 // 1024
    float* kT   = sm + 1024;          // 32 rows (e) x 420 (y, padded)
    float* att  = kT + 32 * 420;      // 32 x 416
    float* c_sh = att + 32 * 416;     // 416

    int tid = threadIdx.x;
    int bid = blockIdx.x;             // 128*8*13
    int tile = bid % 13;
    int bh = bid / 13;
    int h = bh & 7, b = bh >> 3;
    int x0 = tile * 32;
    size_t baseBH = (size_t)(b * Hh + h) * Ss;

    // loads
    const float* qb = g_q + (baseBH + x0) * Ee;
#pragma unroll
    for (int i = tid; i < 1024; i += 256) q_sh[i] = qb[i];
    const float* kb = g_k + baseBH * Ee;
    for (int i = tid; i < Ss * Ee; i += 256) {
        int y = i >> 5, e = i & 31;
        kT[e * 420 + y] = kb[i];
    }
    for (int i = tid; i < Ss; i += 256) {
        float val = (i < Nn) ? pmask[b * Nn + i] : mmask[b * Mm + (i - Nn)];
        c_sh[i] = (val == -2.0f) ? 0.f : 1.f;
    }
    __syncthreads();

    // ---- scores: thread (xg=tid/32, lane) does 4x x 4y register tiles ----
    const float scale = 0.1767766952966369f;   // 1/sqrt(32)
    int xg = tid >> 5;
    int lane = tid & 31;
    bool xIsP = (x0 == 0);                     // tile 0 holds the N=32 P rows
    for (int yq = lane; yq < 104; yq += 32) {
        int y0 = yq << 2;
        float4 acc[4];
#pragma unroll
        for (int i = 0; i < 4; i++) acc[i] = make_float4(0.f, 0.f, 0.f, 0.f);
#pragma unroll 8
        for (int e = 0; e < 32; e++) {
            float4 kv = *(const float4*)&kT[e * 420 + y0];
#pragma unroll
            for (int i = 0; i < 4; i++) {
                float a = q_sh[(xg * 4 + i) * 32 + e];
                acc[i].x = fmaf(a, kv.x, acc[i].x);
                acc[i].y = fmaf(a, kv.y, acc[i].y);
                acc[i].z = fmaf(a, kv.z, acc[i].z);
                acc[i].w = fmaf(a, kv.w, acc[i].w);
            }
        }
        float4 cy = *(const float4*)&c_sh[y0];
        bool cross = (xIsP != (y0 < Nn));      // quads never straddle y=32
#pragma unroll
        for (int i = 0; i < 4; i++) {
            float cxi = c_sh[x0 + xg * 4 + i];
            float mx_ = cross ? cxi * cy.x : 0.f;
            float my_ = cross ? cxi * cy.y : 0.f;
            float mz_ = cross ? cxi * cy.z : 0.f;
            float mw_ = cross ? cxi * cy.w : 0.f;
            float4 r;
            r.x = acc[i].x * scale + (1.f - mx_) * (-1.0e9f);
            r.y = acc[i].y * scale + (1.f - my_) * (-1.0e9f);
            r.z = acc[i].z * scale + (1.f - mz_) * (-1.0e9f);
            r.w = acc[i].w * scale + (1.f - mw_) * (-1.0e9f);
            *(float4*)&att[(xg * 4 + i) * 416 + y0] = r;
        }
    }
    __syncthreads();

    // ---- softmax: warp w handles rows w, w+8, w+16, w+24 (416 = 13*32) ---
    int w = tid >> 5;
#pragma unroll
    for (int rr = 0; rr < 4; rr++) {
        int xr = w + rr * 8;
        float* row = att + xr * 416;
        float mx = -3.0e38f;
#pragma unroll
        for (int j = 0; j < 13; j++) mx = fmaxf(mx, row[lane + 32 * j]);
        mx = warpMax(mx);
        float ev[13];
        float ssum = 0.f;
#pragma unroll
        for (int j = 0; j < 13; j++) {
            ev[j] = __expf(row[lane + 32 * j] - mx);
            ssum += ev[j];
        }
        ssum = warpSum(ssum);
        // masked entries already exp->0; fully-padded rows zeroed by c[x].
        float inv = c_sh[x0 + xr] / ssum;
#pragma unroll
        for (int j = 0; j < 13; j++) row[lane + 32 * j] = ev[j] * inv;
    }
    __syncthreads();

    // ---- AV: warp w owns rows 4w..4w+3, lane = e ----
    const float* vb = g_v + baseBH * Ee;
    float o0 = 0.f, o1 = 0.f, o2 = 0.f, o3 = 0.f;
    const float* ar = att + (w * 4) * 416;
#pragma unroll 4
    for (int y = 0; y < 416; y++) {
        float vv = vb[y * 32 + lane];
        o0 = fmaf(ar[y],        vv, o0);
        o1 = fmaf(ar[416 + y],  vv, o1);
        o2 = fmaf(ar[832 + y],  vv, o2);
        o3 = fmaf(ar[1248 + y], vv, o3);
    }
    float ov[4] = {o0, o1, o2, o3};
#pragma unroll
    for (int i = 0; i < 4; i++) {
        int xs_ = x0 + w * 4 + i;
        float gv = g_g[(baseBH + xs_) * Ee + lane];
        float sg = 1.f / (1.f + __expf(-gv));
        g_ao[((size_t)b * Ss + xs_) * Oo + h * Ee + lane] = ov[i] * sg;
    }
}

// ============ Kernel 4: output projection + LN2, 8 rows per block ==========
__global__ void k_outln(const float* __restrict__ wmat,
                        const float* __restrict__ bias,
                        const float* __restrict__ g2,
                        const float* __restrict__ b2,
                        float* __restrict__ out) {
    __shared__ float xs[8 * 256];
    __shared__ float ys[8 * 257];
    __shared__ float mus[8], rss[8];
    int t = threadIdx.x;
    int r0 = blockIdx.x * 8;

    for (int i = t; i < 2048; i += 256) xs[i] = g_ao[(size_t)r0 * 256 + i];
    __syncthreads();

    float acc[8];
    float bb = bias[t];
#pragma unroll
    for (int r = 0; r < 8; r++) acc[r] = bb;
#pragma unroll 2
    for (int kk = 0; kk < 256; kk++) {
        float wv = wmat[kk * 256 + t];
#pragma unroll
        for (int r = 0; r < 8; r++) acc[r] = fmaf(xs[r * 256 + kk], wv, acc[r]);
    }
#pragma unroll
    for (int r = 0; r < 8; r++) ys[r * 257 + t] = acc[r];
    __syncthreads();

    int w = t >> 5, lane = t & 31;
    // warp w reduces row w
    float s = 0.f;
#pragma unroll
    for (int j = 0; j < 8; j++) s += ys[w * 257 + lane + 32 * j];
    s = warpSum(s);
    float mu = s * (1.f / 256.f);
    float vs = 0.f;
#pragma unroll
    for (int j = 0; j < 8; j++) {
        float d = ys[w * 257 + lane + 32 * j] - mu;
        vs += d * d;
    }
    vs = warpSum(vs);
    if (lane == 0) { mus[w] = mu; rss[w] = rsqrtf(vs * (1.f / 256.f) + 1e-6f); }
    __syncthreads();

    float gt = g2[t], bt = b2[t];
#pragma unroll
    for (int r = 0; r < 8; r++) {
        out[(size_t)(r0 + r) * 256 + t] =
            (ys[r * 257 + t] - mus[r]) * rss[r] * gt + bt;
    }
}

// ===========================================================================
extern "C" void kernel_launch(void* const* d_in, const int* in_sizes, int n_in,
                              void* d_out, int out_size) {
    const float* x   = (const float*)d_in[0];
    const float* pm  = (const float*)d_in[1];
    const float* mm  = (const float*)d_in[2];
    const float* qp  = (const float*)d_in[3];
    const float* kp  = (const float*)d_in[4];
    const float* vp  = (const float*)d_in[5];
    const float* gp  = (const float*)d_in[6];
    const float* ow  = (const float*)d_in[7];
    const float* ob  = (const float*)d_in[8];
    const float* l1g = (const float*)d_in[9];
    const float* l1b = (const float*)d_in[10];
    const float* l2g = (const float*)d_in[11];
    const float* l2b = (const float*)d_in[12];
    float* out = (float*)d_out;

    const int attn_smem = (1024 + 32 * 420 + 32 * 416 + 416) * 4;  // 112768
    cudaFuncSetAttribute(k_attn, cudaFuncAttributeMaxDynamicSharedMemorySize,
                         attn_smem);

    k_ln1 <<<BSs, 256>>>(x, l1g, l1b);
    k_qkvg<<<dim3(832, 16), 256>>>(qp, kp, vp, gp);
    k_attn<<<Bb * Hh * 13, 256, attn_smem>>>(pm, mm);
    k_outln<<<BSs / 8, 256>>>(ow, ob, l2g, l2b, out);
}

// round 2
// speedup vs baseline: 1.5295x; 1.5295x over previous
#include <cuda_runtime.h>

#define Bb   128
#define Ss   416
#define Nn   32
#define Mm   384
#define Dd   256
#define Hh   8
#define Ee   32
#define Oo   256
#define BSs  (Bb*Ss)          // 53248

// -------- scratch (static device globals; no runtime allocation) ----------
__device__ float g_xln[BSs*Dd];        // LN1(x)
__device__ float g_q  [Bb*Hh*Ss*Ee];
__device__ float g_k  [Bb*Hh*Ss*Ee];
__device__ float g_v  [Bb*Hh*Ss*Ee];
__device__ float g_g  [Bb*Hh*Ss*Ee];
__device__ float g_ao [BSs*Oo];        // attention output, [B,S,H*E]

__device__ __forceinline__ float warpSum(float v) {
#pragma unroll
    for (int o = 16; o; o >>= 1) v += __shfl_xor_sync(0xffffffffu, v, o);
    return v;
}
__device__ __forceinline__ float warpMax(float v) {
#pragma unroll
    for (int o = 16; o; o >>= 1) v = fmaxf(v, __shfl_xor_sync(0xffffffffu, v, o));
    return v;
}

// =================== Kernel 1: LayerNorm over D=256 =======================
__global__ void k_ln1(const float* __restrict__ x,
                      const float* __restrict__ gam,
                      const float* __restrict__ bet) {
    int row = blockIdx.x;
    int t = threadIdx.x;
    int w = t >> 5, lane = t & 31;
    __shared__ float red[8];

    float v = x[(size_t)row * Dd + t];
    float s = warpSum(v);
    if (lane == 0) red[w] = s;
    __syncthreads();
    float mu = 0.f;
#pragma unroll
    for (int i = 0; i < 8; i++) mu += red[i];
    mu *= (1.f / 256.f);
    float d = v - mu;
    __syncthreads();
    s = warpSum(d * d);
    if (lane == 0) red[w] = s;
    __syncthreads();
    float var = 0.f;
#pragma unroll
    for (int i = 0; i < 8; i++) var += red[i];
    var *= (1.f / 256.f);
    g_xln[(size_t)row * Dd + t] = d * rsqrtf(var + 1e-6f) * gam[t] + bet[t];
}

// ============ Kernel 2: QKVG projections, 128x128 tile, 8x8 microtile =====
// C[53248 x 1024] = xln[53248 x 256] * W[256 x 1024] (4 projections of 256).
__global__ void __launch_bounds__(256, 2)
k_qkvg(const float* __restrict__ qp, const float* __restrict__ kp,
       const float* __restrict__ vp, const float* __restrict__ gp) {
    __shared__ float As[16 * 132];   // [k][m], stride 132
    __shared__ float Bs[16 * 132];   // [k][n], stride 132

    int tid  = threadIdx.x;
    int warp = tid >> 5, lane = tid & 31;
    int cx = (warp & 1) * 8 + (lane & 7);    // 0..15 (col group)
    int cy = (warp >> 1) * 4 + (lane >> 3);  // 0..15 (row group)

    int m0 = blockIdx.x * 128;
    int n0 = blockIdx.y * 128;
    int proj = n0 >> 8;
    const float* W = (proj == 0) ? qp : (proj == 1) ? kp : (proj == 2) ? vp : gp;
    float*      Og = (proj == 0) ? g_q : (proj == 1) ? g_k : (proj == 2) ? g_v : g_g;
    int nin = n0 & 255;

    float acc[8][8];
#pragma unroll
    for (int i = 0; i < 8; i++)
#pragma unroll
        for (int j = 0; j < 8; j++) acc[i][j] = 0.f;

    for (int k0 = 0; k0 < 256; k0 += 16) {
        // stage A tile 128x16 -> As[k][m]
#pragma unroll
        for (int it = 0; it < 2; it++) {
            int i = tid + it * 256;
            int m = i >> 2, kq = i & 3;
            float4 a4 = *(const float4*)&g_xln[(size_t)(m0 + m) * Dd + k0 + kq * 4];
            As[(kq * 4 + 0) * 132 + m] = a4.x;
            As[(kq * 4 + 1) * 132 + m] = a4.y;
            As[(kq * 4 + 2) * 132 + m] = a4.z;
            As[(kq * 4 + 3) * 132 + m] = a4.w;
        }
        // stage B tile 16x128 -> Bs[k][n]
#pragma unroll
        for (int it = 0; it < 2; it++) {
            int i = tid + it * 256;
            int nq = i & 31, kk = i >> 5;
            int n = nin + nq * 4;
            int h = n >> 5, e = n & 31;
            float4 b4 = *(const float4*)&W[h * 8192 + (k0 + kk) * 32 + e];
            *(float4*)&Bs[kk * 132 + nq * 4] = b4;
        }
        __syncthreads();
#pragma unroll 4
        for (int kk = 0; kk < 16; kk++) {
            float a[8], b[8];
            *(float4*)&a[0] = *(const float4*)&As[kk * 132 + cy * 8];
            *(float4*)&a[4] = *(const float4*)&As[kk * 132 + cy * 8 + 4];
            *(float4*)&b[0] = *(const float4*)&Bs[kk * 132 + cx * 8];
            *(float4*)&b[4] = *(const float4*)&Bs[kk * 132 + cx * 8 + 4];
#pragma unroll
            for (int i = 0; i < 8; i++)
#pragma unroll
                for (int j = 0; j < 8; j++)
                    acc[i][j] = fmaf(a[i], b[j], acc[i][j]);
        }
        __syncthreads();
    }

    // write out: [B,H,S,E]
#pragma unroll
    for (int i = 0; i < 8; i++) {
        int m = m0 + cy * 8 + i;
        int b = m / Ss;
        int s = m - b * Ss;
#pragma unroll
        for (int jg = 0; jg < 2; jg++) {
            int n = nin + cx * 8 + jg * 4;
            int h = n >> 5, e = n & 31;
            float4 v4 = make_float4(acc[i][jg * 4 + 0], acc[i][jg * 4 + 1],
                                    acc[i][jg * 4 + 2], acc[i][jg * 4 + 3]);
            *(float4*)&Og[(((size_t)(b * Hh + h)) * Ss + s) * Ee + e] = v4;
        }
    }
}

// ============ Kernel 3: fused attention, one block per (b,h) ==============
// smem: kT[32*420] | v[416*33] | att[32*416] | q[1024] | c[416] = 167680 B
__global__ void k_attn(const float* __restrict__ pmask,
                       const float* __restrict__ mmask) {
    extern __shared__ float sm[];
    float* kT   = sm;                        // e-major: kT[e*420 + y]
    float* v_sh = kT + 32 * 420;             // v_sh[y*33 + e]
    float* att  = v_sh + 416 * 33;           // att[x*416 + y]
    float* q_sh = att + 32 * 416;            // q_sh[x*32 + e]
    float* c_sh = q_sh + 1024;               // 416

    int tid = threadIdx.x;
    int bh = blockIdx.x;                     // 0..1023
    int h = bh & 7, b = bh >> 3;
    size_t baseBH = (size_t)(b * Hh + h) * Ss;

    // one-time loads: K (transposed), V, combined mask
    const float* kb = g_k + baseBH * Ee;
    for (int i = tid; i < Ss * Ee; i += 256) {
        int y = i >> 5, e = i & 31;
        kT[e * 420 + y] = kb[i];
    }
    const float* vb = g_v + baseBH * Ee;
    for (int i = tid; i < Ss * Ee; i += 256) {
        int y = i >> 5, e = i & 31;
        v_sh[y * 33 + e] = vb[i];
    }
    for (int i = tid; i < Ss; i += 256) {
        float val = (i < Nn) ? pmask[b * Nn + i] : mmask[b * Mm + (i - Nn)];
        c_sh[i] = (val == -2.0f) ? 0.f : 1.f;
    }
    __syncthreads();

    const float scale = 0.1767766952966369f;   // 1/sqrt(32)
    int w = tid >> 5;
    int lane = tid & 31;
    int xg = w;

    for (int tile = 0; tile < 13; tile++) {
        int x0 = tile * 32;
        // stage Q tile
        const float* qb = g_q + (baseBH + x0) * Ee;
#pragma unroll
        for (int i = tid; i < 1024; i += 256) q_sh[i] = qb[i];
        __syncthreads();

        // ---- scores ----
        bool xIsP = (tile == 0);
        for (int yq = lane; yq < 104; yq += 32) {
            int y0 = yq << 2;
            float4 acc[4];
#pragma unroll
            for (int i = 0; i < 4; i++) acc[i] = make_float4(0.f, 0.f, 0.f, 0.f);
#pragma unroll 8
            for (int e = 0; e < 32; e++) {
                float4 kv = *(const float4*)&kT[e * 420 + y0];
#pragma unroll
                for (int i = 0; i < 4; i++) {
                    float a = q_sh[(xg * 4 + i) * 32 + e];
                    acc[i].x = fmaf(a, kv.x, acc[i].x);
                    acc[i].y = fmaf(a, kv.y, acc[i].y);
                    acc[i].z = fmaf(a, kv.z, acc[i].z);
                    acc[i].w = fmaf(a, kv.w, acc[i].w);
                }
            }
            float4 cy = *(const float4*)&c_sh[y0];
            bool cross = (xIsP != (y0 < Nn));
#pragma unroll
            for (int i = 0; i < 4; i++) {
                float cxi = c_sh[x0 + xg * 4 + i];
                float mx_ = cross ? cxi * cy.x : 0.f;
                float my_ = cross ? cxi * cy.y : 0.f;
                float mz_ = cross ? cxi * cy.z : 0.f;
                float mw_ = cross ? cxi * cy.w : 0.f;
                float4 r;
                r.x = acc[i].x * scale + (1.f - mx_) * (-1.0e9f);
                r.y = acc[i].y * scale + (1.f - my_) * (-1.0e9f);
                r.z = acc[i].z * scale + (1.f - mz_) * (-1.0e9f);
                r.w = acc[i].w * scale + (1.f - mw_) * (-1.0e9f);
                *(float4*)&att[(xg * 4 + i) * 416 + y0] = r;
            }
        }
        __syncthreads();

        // ---- softmax: warp w handles rows w, w+8, w+16, w+24 ----
#pragma unroll
        for (int rr = 0; rr < 4; rr++) {
            int xr = w + rr * 8;
            float* row = att + xr * 416;
            float mx = -3.0e38f;
#pragma unroll
            for (int j = 0; j < 13; j++) mx = fmaxf(mx, row[lane + 32 * j]);
            mx = warpMax(mx);
            float ev[13];
            float ssum = 0.f;
#pragma unroll
            for (int j = 0; j < 13; j++) {
                ev[j] = __expf(row[lane + 32 * j] - mx);
                ssum += ev[j];
            }
            ssum = warpSum(ssum);
            float inv = c_sh[x0 + xr] / ssum;
#pragma unroll
            for (int j = 0; j < 13; j++) row[lane + 32 * j] = ev[j] * inv;
        }
        __syncthreads();

        // ---- AV from smem: warp w owns rows 4w..4w+3, lane = e ----
        const float* ar = att + (w * 4) * 416;
        float o0 = 0.f, o1 = 0.f, o2 = 0.f, o3 = 0.f;
#pragma unroll 2
        for (int y = 0; y < 416; y += 4) {
            float4 a0 = *(const float4*)&ar[y];
            float4 a1 = *(const float4*)&ar[416 + y];
            float4 a2 = *(const float4*)&ar[832 + y];
            float4 a3 = *(const float4*)&ar[1248 + y];
            float vv0 = v_sh[(y + 0) * 33 + lane];
            float vv1 = v_sh[(y + 1) * 33 + lane];
            float vv2 = v_sh[(y + 2) * 33 + lane];
            float vv3 = v_sh[(y + 3) * 33 + lane];
            o0 = fmaf(a0.x, vv0, fmaf(a0.y, vv1, fmaf(a0.z, vv2, fmaf(a0.w, vv3, o0))));
            o1 = fmaf(a1.x, vv0, fmaf(a1.y, vv1, fmaf(a1.z, vv2, fmaf(a1.w, vv3, o1))));
            o2 = fmaf(a2.x, vv0, fmaf(a2.y, vv1, fmaf(a2.z, vv2, fmaf(a2.w, vv3, o2))));
            o3 = fmaf(a3.x, vv0, fmaf(a3.y, vv1, fmaf(a3.z, vv2, fmaf(a3.w, vv3, o3))));
        }
        float ov[4] = {o0, o1, o2, o3};
#pragma unroll
        for (int i = 0; i < 4; i++) {
            int xs_ = x0 + w * 4 + i;
            float gv = g_g[(baseBH + xs_) * Ee + lane];
            float sg = 1.f / (1.f + __expf(-gv));
            g_ao[((size_t)b * Ss + xs_) * Oo + h * Ee + lane] = ov[i] * sg;
        }
        __syncthreads();
    }
}

// ============ Kernel 4: output projection + LN2, 16 rows per block =========
__global__ void k_outln(const float* __restrict__ wmat,
                        const float* __restrict__ bias,
                        const float* __restrict__ g2,
                        const float* __restrict__ b2,
                        float* __restrict__ out) {
    __shared__ float xs[16 * 256];
    __shared__ float ys[16 * 257];
    __shared__ float mus[16], rss[16];
    int t = threadIdx.x;
    int r0 = blockIdx.x * 16;

    for (int i = t; i < 1024; i += 256) {
        *(float4*)&xs[i * 4] = *(const float4*)&g_ao[(size_t)r0 * 256 + i * 4];
    }
    __syncthreads();

    float acc[16];
    float bb = bias[t];
#pragma unroll
    for (int r = 0; r < 16; r++) acc[r] = bb;
#pragma unroll 4
    for (int k4 = 0; k4 < 64; k4++) {
        int kk = k4 * 4;
        float w0 = wmat[(kk + 0) * 256 + t];
        float w1 = wmat[(kk + 1) * 256 + t];
        float w2 = wmat[(kk + 2) * 256 + t];
        float w3 = wmat[(kk + 3) * 256 + t];
#pragma unroll
        for (int r = 0; r < 16; r++) {
            float4 xv = *(const float4*)&xs[r * 256 + kk];
            acc[r] = fmaf(xv.x, w0, fmaf(xv.y, w1, fmaf(xv.z, w2, fmaf(xv.w, w3, acc[r]))));
        }
    }
#pragma unroll
    for (int r = 0; r < 16; r++) ys[r * 257 + t] = acc[r];
    __syncthreads();

    int w = t >> 5, lane = t & 31;
#pragma unroll
    for (int half = 0; half < 2; half++) {
        int rr = w + half * 8;
        float s = 0.f;
#pragma unroll
        for (int j = 0; j < 8; j++) s += ys[rr * 257 + lane + 32 * j];
        s = warpSum(s);
        float mu = s * (1.f / 256.f);
        float vs = 0.f;
#pragma unroll
        for (int j = 0; j < 8; j++) {
            float d = ys[rr * 257 + lane + 32 * j] - mu;
            vs += d * d;
        }
        vs = warpSum(vs);
        if (lane == 0) { mus[rr] = mu; rss[rr] = rsqrtf(vs * (1.f / 256.f) + 1e-6f); }
    }
    __syncthreads();

    float gt = g2[t], bt = b2[t];
#pragma unroll
    for (int r = 0; r < 16; r++) {
        out[(size_t)(r0 + r) * 256 + t] =
            (ys[r * 257 + t] - mus[r]) * rss[r] * gt + bt;
    }
}

// ===========================================================================
extern "C" void kernel_launch(void* const* d_in, const int* in_sizes, int n_in,
                              void* d_out, int out_size) {
    const float* x   = (const float*)d_in[0];
    const float* pm  = (const float*)d_in[1];
    const float* mm  = (const float*)d_in[2];
    const float* qp  = (const float*)d_in[3];
    const float* kp  = (const float*)d_in[4];
    const float* vp  = (const float*)d_in[5];
    const float* gp  = (const float*)d_in[6];
    const float* ow  = (const float*)d_in[7];
    const float* ob  = (const float*)d_in[8];
    const float* l1g = (const float*)d_in[9];
    const float* l1b = (const float*)d_in[10];
    const float* l2g = (const float*)d_in[11];
    const float* l2b = (const float*)d_in[12];
    float* out = (float*)d_out;

    const int attn_smem = (32 * 420 + 416 * 33 + 32 * 416 + 1024 + 416) * 4; // 167680
    cudaFuncSetAttribute(k_attn, cudaFuncAttributeMaxDynamicSharedMemorySize,
                         attn_smem);

    k_ln1 <<<BSs, 256>>>(x, l1g, l1b);
    k_qkvg<<<dim3(416, 8), 256>>>(qp, kp, vp, gp);
    k_attn<<<Bb * Hh, 256, attn_smem>>>(pm, mm);
    k_outln<<<BSs / 16, 256>>>(ow, ob, l2g, l2b, out);
}